// round 6
// baseline (speedup 1.0000x reference)
#include <cuda_runtime.h>
#include <math.h>

#define B_ 64
#define T_ 1024
#define I_ 128
#define H_ 512
#define O_ 128
#define GRID0 128
#define NT 512
#define KC 64
#define CHUNK (KC * B_)          // 4096 floats per staged chunk
#define WST0 645                 // 640 + 5 (5 mod 32 -> conflict-free rows)
#define WST1 1029                // 1024 + 5

typedef unsigned long long ull;

// ---- scratch (device globals: allocation-free) ----
__device__ float g_xT[T_ * I_ * B_];      // x transposed: [t][i][b]
__device__ float g_h0buf[2 * H_ * B_];    // layer0 h double buffer
__device__ float g_h1[T_ * H_ * B_];      // layer1 h history: [t][h][b]
__device__ unsigned g_bar_count;
__device__ unsigned g_bar_sense;

// ---- packed f32x2 helpers ----
__device__ __forceinline__ ull pack2(float x) {
    ull r; unsigned u = __float_as_uint(x);
    asm("mov.b64 %0, {%1, %1};" : "=l"(r) : "r"(u));
    return r;
}
__device__ __forceinline__ void ffma2(ull &acc, ull a, ull w) {
    asm("fma.rn.f32x2 %0, %1, %2, %0;" : "+l"(acc) : "l"(a), "l"(w));
}
__device__ __forceinline__ float lo2(ull v) { return __uint_as_float((unsigned)v); }
__device__ __forceinline__ float hi2(ull v) { return __uint_as_float((unsigned)(v >> 32)); }

__device__ __forceinline__ void cp16(float* dst, const float* src) {
    unsigned ds = (unsigned)__cvta_generic_to_shared(dst);
    asm volatile("cp.async.cg.shared.global [%0], [%1], 16;" :: "r"(ds), "l"(src));
}

__device__ __forceinline__ float sigm(float x) {
    return __fdividef(1.f, 1.f + __expf(-x));
}
__device__ __forceinline__ float tanh_(float x) {
    return __fdividef(2.f, 1.f + __expf(-2.f * x)) - 1.f;
}

// ---- grid barrier: atomic arrive + ld.acquire spin (no atomic polling) ----
__device__ __forceinline__ void gridbar(unsigned &sense) {
    __syncthreads();
    if (threadIdx.x == 0) {
        unsigned s = sense ^ 1u;
        sense = s;
        unsigned old;
        asm volatile("atom.release.gpu.global.add.u32 %0, [%1], %2;"
                     : "=r"(old) : "l"(&g_bar_count), "r"(1u));
        if (old == GRID0 - 1u) {
            g_bar_count = 0u;
            asm volatile("st.release.gpu.global.u32 [%0], %1;"
                         :: "l"(&g_bar_sense), "r"(s));
        } else {
            unsigned v;
            do {
                asm volatile("ld.acquire.gpu.global.u32 %0, [%1];"
                             : "=r"(v) : "l"(&g_bar_sense));
            } while (v != s);
        }
    }
    __syncthreads();
}

// ---- stage one KC x 64 chunk of the input vector into smem via cp.async ----
__device__ __forceinline__ void stage_chunk(
    float* __restrict__ dst,
    const float* __restrict__ srcA, const int len0,
    const float* __restrict__ srcB, const int kb)
{
    const int tid = threadIdx.x;
#pragma unroll
    for (int it = 0; it < 2; it++) {
        int v = tid + it * NT;            // 0..1023 float4 slots
        int kk = v >> 4, c4 = (v & 15) << 2;
        int kg = kb + kk;
        float* d = dst + v * 4;
        if (kg < len0)      cp16(d, srcA + kg * B_ + c4);
        else if (srcB)      cp16(d, srcB + (kg - len0) * B_ + c4);
        else                *(float4*)d = make_float4(0.f, 0.f, 0.f, 0.f);
    }
    asm volatile("cp.async.commit_group;");
}

// ---- one LSTM step for this CTA's 4 h-columns (16 gate rows) ----
// thread map: bo = tid&3 (16-batch group), jp = (tid>>2)&7 (row pair), ks = tid>>5 (k-split 16)
__device__ __forceinline__ void lstm_step(
    const float* __restrict__ Ws, const int WST, const int nc,
    const float* __restrict__ bias,
    float* __restrict__ ins, float* __restrict__ red,
    const float* __restrict__ srcA, const int len0,
    const float* __restrict__ srcB,
    float* __restrict__ hout, float &cst, const bool pre0)
{
    const int tid = threadIdx.x;
    const int bo = tid & 3;
    const int jp = (tid >> 2) & 7;
    const int ks = tid >> 5;

    ull a0[8], a1[8];
#pragma unroll
    for (int i = 0; i < 8; i++) { a0[i] = 0ull; a1[i] = 0ull; }

    if (!pre0) stage_chunk(ins, srcA, len0, srcB, 0);

    for (int c = 0; c < nc; c++) {
        if (c + 1 < nc) {
            stage_chunk(ins + ((c + 1) & 1) * CHUNK, srcA, len0, srcB, (c + 1) * KC);
            asm volatile("cp.async.wait_group 1;");
        } else {
            asm volatile("cp.async.wait_group 0;");
        }
        __syncthreads();

        const float* buf = ins + (c & 1) * CHUNK;
        const float* ap  = buf + (ks * 4) * B_ + bo * 16;
        const float* w0p = Ws + (2 * jp) * WST + c * KC + ks * 4;
        const float* w1p = w0p + WST;
#pragma unroll
        for (int kk = 0; kk < 4; kk++) {
            const float* a = ap + kk * B_;
            ulonglong2 A0 = *(const ulonglong2*)(a);
            ulonglong2 A1 = *(const ulonglong2*)(a + 4);
            ulonglong2 A2 = *(const ulonglong2*)(a + 8);
            ulonglong2 A3 = *(const ulonglong2*)(a + 12);
            ull w0 = pack2(w0p[kk]);
            ull w1 = pack2(w1p[kk]);
            ffma2(a0[0], A0.x, w0); ffma2(a0[1], A0.y, w0);
            ffma2(a0[2], A1.x, w0); ffma2(a0[3], A1.y, w0);
            ffma2(a0[4], A2.x, w0); ffma2(a0[5], A2.y, w0);
            ffma2(a0[6], A3.x, w0); ffma2(a0[7], A3.y, w0);
            ffma2(a1[0], A0.x, w1); ffma2(a1[1], A0.y, w1);
            ffma2(a1[2], A1.x, w1); ffma2(a1[3], A1.y, w1);
            ffma2(a1[4], A2.x, w1); ffma2(a1[5], A2.y, w1);
            ffma2(a1[6], A3.x, w1); ffma2(a1[7], A3.y, w1);
        }
        __syncthreads();
    }

    // k-split reduction through smem (once per step)
    {
        int rb = ks * 1024 + (2 * jp) * B_ + bo * 16;
#pragma unroll
        for (int p = 0; p < 8; p++) *(ull*)(red + rb + 2 * p) = a0[p];
        rb += B_;
#pragma unroll
        for (int p = 0; p < 8; p++) *(ull*)(red + rb + 2 * p) = a1[p];
    }
    __syncthreads();

    if (tid < 256) {
        int c4 = tid >> 6;
        int b  = tid & 63;
        float xi = bias[c4], xf = bias[4 + c4], xg = bias[8 + c4], xo = bias[12 + c4];
#pragma unroll
        for (int s = 0; s < 16; s++) {
            const float* r = red + s * 1024 + b;
            xi += r[(0  + c4) * B_];
            xf += r[(4  + c4) * B_];
            xg += r[(8  + c4) * B_];
            xo += r[(12 + c4) * B_];
        }
        float ii = sigm(xi), ff = sigm(xf), gg = tanh_(xg), oo = sigm(xo);
        cst = ff * cst + ii * gg;
        hout[c4 * B_ + b] = oo * tanh_(cst);
    }
}

// ---------------------------------------------------------------------------
// Mega kernel: transpose + both LSTM layers (pipelined) + FC, one launch.
__global__ void __launch_bounds__(NT, 1) mega_kernel(
    const float* __restrict__ x,
    const float* __restrict__ W_ih0, const float* __restrict__ W_hh0,
    const float* __restrict__ b_ih0, const float* __restrict__ b_hh0,
    const float* __restrict__ W_ih1, const float* __restrict__ W_hh1,
    const float* __restrict__ b_ih1, const float* __restrict__ b_hh1,
    const float* __restrict__ Wfc,  const float* __restrict__ bfc,
    float* __restrict__ out)
{
    extern __shared__ float sm[];
    float* Ws0   = sm;                      // 16 * 645
    float* Ws1   = Ws0 + 16 * WST0;         // 16 * 1029
    float* bias0 = Ws1 + 16 * WST1;         // 16
    float* bias1 = bias0 + 16;              // 16
    float* ins   = bias1 + 16;              // 2 * CHUNK
    float* red   = ins + 2 * CHUNK;         // 16 * 16 * 64 = 16384

    const int tid = threadIdx.x;
    const int hj0 = blockIdx.x * 4;

    unsigned sense = 0;
    if (tid == 0) sense = *(volatile unsigned*)&g_bar_sense;

    // ---- weight slices: local row r = gate*4 + c <-> global row gate*512 + hj0 + c
    for (int idx = tid; idx < 16 * 640; idx += NT) {
        int r = idx / 640, k = idx - r * 640;
        int grow = (r >> 2) * H_ + hj0 + (r & 3);
        Ws0[r * WST0 + k] = (k < I_) ? W_ih0[grow * I_ + k]
                                     : W_hh0[grow * H_ + (k - I_)];
    }
    for (int idx = tid; idx < 16 * 1024; idx += NT) {
        int r = idx >> 10, k = idx & 1023;
        int grow = (r >> 2) * H_ + hj0 + (r & 3);
        Ws1[r * WST1 + k] = (k < H_) ? W_ih1[grow * H_ + k]
                                     : W_hh1[grow * H_ + (k - H_)];
    }
    if (tid < 16) {
        int grow = (tid >> 2) * H_ + hj0 + (tid & 3);
        bias0[tid] = b_ih0[grow] + b_hh0[grow];
        bias1[tid] = b_ih1[grow] + b_hh1[grow];
    }

    // ---- transpose phase: x[b][t][i] -> g_xT[t][i][b] (tile in red region)
    {
        float (*tile)[I_ + 1] = (float (*)[I_ + 1])red;   // 64 x 129
        for (int t = blockIdx.x; t < T_; t += GRID0) {
            __syncthreads();
            for (int idx = tid; idx < B_ * I_; idx += NT) {
                int b = idx >> 7, i = idx & 127;
                tile[b][i] = x[(b * T_ + t) * I_ + i];
            }
            __syncthreads();
            for (int idx = tid; idx < B_ * I_; idx += NT) {
                int b = idx & 63, i = idx >> 6;
                g_xT[t * I_ * B_ + i * B_ + b] = tile[b][i];
            }
        }
    }
    gridbar(sense);

    // ---- main pipelined loop: layer0 at t=k, layer1 at s=k-1
    float c0st = 0.f, c1st = 0.f;
    for (int k = 0; k <= T_; ++k) {
        if (k < T_) {
            const float* srcB = (k > 0) ? (g_h0buf + ((k - 1) & 1) * H_ * B_)
                                        : (const float*)0;
            lstm_step(Ws0, WST0, 640 / KC, bias0, ins, red,
                      g_xT + k * I_ * B_, I_, srcB,
                      g_h0buf + (k & 1) * H_ * B_ + hj0 * B_, c0st, k > 0);
        }
        if (k >= 1) {
            int s = k - 1;
            const float* srcB = (s > 0) ? (g_h1 + (s - 1) * H_ * B_)
                                        : (const float*)0;
            lstm_step(Ws1, WST1, 1024 / KC, bias1, ins, red,
                      g_h0buf + (s & 1) * H_ * B_, H_, srcB,
                      g_h1 + s * H_ * B_ + hj0 * B_, c1st, false);
        }
        // prefetch next layer0 chunk 0 (pure x, static data) across the barrier
        if (k + 1 < T_) {
            stage_chunk(ins, g_xT + (k + 1) * I_ * B_, I_, (const float*)0, 0);
        }
        gridbar(sense);
    }

    // ---- FC phase: out[b][t][o] = sum_h h1[t][h][b] * Wfc[o][h] + bfc[o]
    {
        float* w_s = red;                 // 128 * 65 = 8320
        float* h_s = red + 128 * 65;      // 64 * 64  = 4096
        const int o  = tid & 127;
        const int bq = tid >> 7;          // 0..3 -> batch 16bq..16bq+15
        const float bfc_r = __ldg(&bfc[o]);

        for (int t = blockIdx.x; t < T_; t += GRID0) {
            ull acc[8];
#pragma unroll
            for (int p = 0; p < 8; p++) acc[p] = 0ull;

            for (int kb = 0; kb < H_; kb += 64) {
                __syncthreads();
                for (int idx = tid; idx < O_ * 64; idx += NT) {
                    int oo = idx >> 6, kk = idx & 63;
                    w_s[oo * 65 + kk] = Wfc[oo * H_ + kb + kk];
                }
                for (int idx = tid; idx < 64 * B_; idx += NT) {
                    h_s[idx] = g_h1[(t * H_ + kb) * B_ + idx];
                }
                __syncthreads();
#pragma unroll 8
                for (int kk = 0; kk < 64; kk++) {
                    const float* a = h_s + kk * B_ + bq * 16;
                    ulonglong2 A0 = *(const ulonglong2*)(a);
                    ulonglong2 A1 = *(const ulonglong2*)(a + 4);
                    ulonglong2 A2 = *(const ulonglong2*)(a + 8);
                    ulonglong2 A3 = *(const ulonglong2*)(a + 12);
                    ull w = pack2(w_s[o * 65 + kk]);
                    ffma2(acc[0], A0.x, w); ffma2(acc[1], A0.y, w);
                    ffma2(acc[2], A1.x, w); ffma2(acc[3], A1.y, w);
                    ffma2(acc[4], A2.x, w); ffma2(acc[5], A2.y, w);
                    ffma2(acc[6], A3.x, w); ffma2(acc[7], A3.y, w);
                }
            }
#pragma unroll
            for (int p = 0; p < 8; p++) {
                int b = bq * 16 + 2 * p;
                out[(b * T_ + t) * O_ + o]       = lo2(acc[p]) + bfc_r;
                out[((b + 1) * T_ + t) * O_ + o] = hi2(acc[p]) + bfc_r;
            }
        }
    }
}

// ---------------------------------------------------------------------------
extern "C" void kernel_launch(void* const* d_in, const int* in_sizes, int n_in,
                              void* d_out, int out_size) {
    const float* x     = (const float*)d_in[0];
    const float* W_ih0 = (const float*)d_in[1];
    const float* W_hh0 = (const float*)d_in[2];
    const float* b_ih0 = (const float*)d_in[3];
    const float* b_hh0 = (const float*)d_in[4];
    const float* W_ih1 = (const float*)d_in[5];
    const float* W_hh1 = (const float*)d_in[6];
    const float* b_ih1 = (const float*)d_in[7];
    const float* b_hh1 = (const float*)d_in[8];
    const float* W_fc  = (const float*)d_in[9];
    const float* b_fc  = (const float*)d_in[10];
    float* out = (float*)d_out;

    size_t smem = (size_t)(16 * WST0 + 16 * WST1 + 32 + 2 * CHUNK + 16384) * sizeof(float);
    cudaFuncSetAttribute(mega_kernel, cudaFuncAttributeMaxDynamicSharedMemorySize, (int)smem);

    mega_kernel<<<GRID0, NT, smem>>>(x, W_ih0, W_hh0, b_ih0, b_hh0,
                                     W_ih1, W_hh1, b_ih1, b_hh1,
                                     W_fc, b_fc, out);
}

// round 8
// speedup vs baseline: 1.6849x; 1.6849x over previous
#include <cuda_runtime.h>
#include <math.h>

#define B_ 64
#define T_ 1024
#define I_ 128
#define H_ 512
#define O_ 128
#define GRID0 128
#define NT 256

typedef unsigned long long ull;

// ---- scratch (device globals: allocation-free) ----
__device__ float g_xT[T_ * I_ * B_];      // x transposed: [t][i][b]
__device__ float g_h0buf[2 * H_ * B_];    // layer0 h double buffer
__device__ float g_h1[T_ * H_ * B_];      // layer1 h history: [t][h][b]
__device__ unsigned g_bar_count;
__device__ unsigned g_bar_sense;

// ---- packed f32x2 helpers ----
__device__ __forceinline__ ull pack2(float x) {
    ull r; unsigned u = __float_as_uint(x);
    asm("mov.b64 %0, {%1, %1};" : "=l"(r) : "r"(u));
    return r;
}
__device__ __forceinline__ void ffma2(ull &acc, ull a, ull w) {
    asm("fma.rn.f32x2 %0, %1, %2, %0;" : "+l"(acc) : "l"(a), "l"(w));
}
__device__ __forceinline__ ull addx2(ull a, ull b) {
    ull r;
    asm("add.rn.f32x2 %0, %1, %2;" : "=l"(r) : "l"(a), "l"(b));
    return r;
}
__device__ __forceinline__ float lo2(ull v) { return __uint_as_float((unsigned)v); }
__device__ __forceinline__ float hi2(ull v) { return __uint_as_float((unsigned)(v >> 32)); }

__device__ __forceinline__ ull shflx16(ull v) {
    unsigned lo = (unsigned)v, hi = (unsigned)(v >> 32);
    lo = __shfl_xor_sync(0xffffffffu, lo, 16);
    hi = __shfl_xor_sync(0xffffffffu, hi, 16);
    return (ull)lo | ((ull)hi << 32);
}

__device__ __forceinline__ float sigm(float x) {
    return __fdividef(1.f, 1.f + __expf(-x));
}
__device__ __forceinline__ float tanh_(float x) {
    return __fdividef(2.f, 1.f + __expf(-2.f * x)) - 1.f;
}

// ---- grid barrier (identical to round-5/6 passing kernel) ----
__device__ __forceinline__ void gridbar(unsigned &sense) {
    __syncthreads();
    if (threadIdx.x == 0) {
        unsigned s = sense ^ 1u;
        sense = s;
        unsigned old;
        asm volatile("atom.release.gpu.global.add.u32 %0, [%1], %2;"
                     : "=r"(old) : "l"(&g_bar_count), "r"(1u));
        if (old == GRID0 - 1u) {
            g_bar_count = 0u;
            asm volatile("st.release.gpu.global.u32 [%0], %1;"
                         :: "l"(&g_bar_sense), "r"(s));
        } else {
            unsigned v;
            do {
                asm volatile("ld.acquire.gpu.global.u32 %0, [%1];"
                             : "=r"(v) : "l"(&g_bar_sense));
            } while (v != s);
        }
    }
    __syncthreads();
}

// ---- gate GEMM over one source segment ----
// Per 16-k block this thread handles k = block*16 + koff.
// acc[r*4 + p]: row rg*8+r (r=0..7), batch ull p (batches bo*8 + 2p, 2p+1).
__device__ __forceinline__ void gate_gemm_seg(
    ull acc[32], const float* __restrict__ src, const float* __restrict__ Wt,
    int nblk, int koff, int bo, int rg)
{
    const float* ap = src + koff * B_ + bo * 8;
    const float* wp = Wt + koff * 16 + rg * 8;
#pragma unroll 4
    for (int c = 0; c < nblk; c++) {
        ulonglong2 Av0 = __ldcg((const ulonglong2*)ap);
        ulonglong2 Av1 = __ldcg((const ulonglong2*)(ap + 4));
        float4 w0 = *(const float4*)(wp);
        float4 w1 = *(const float4*)(wp + 4);
        ull W;
        W = pack2(w0.x);
        ffma2(acc[0],  Av0.x, W); ffma2(acc[1],  Av0.y, W);
        ffma2(acc[2],  Av1.x, W); ffma2(acc[3],  Av1.y, W);
        W = pack2(w0.y);
        ffma2(acc[4],  Av0.x, W); ffma2(acc[5],  Av0.y, W);
        ffma2(acc[6],  Av1.x, W); ffma2(acc[7],  Av1.y, W);
        W = pack2(w0.z);
        ffma2(acc[8],  Av0.x, W); ffma2(acc[9],  Av0.y, W);
        ffma2(acc[10], Av1.x, W); ffma2(acc[11], Av1.y, W);
        W = pack2(w0.w);
        ffma2(acc[12], Av0.x, W); ffma2(acc[13], Av0.y, W);
        ffma2(acc[14], Av1.x, W); ffma2(acc[15], Av1.y, W);
        W = pack2(w1.x);
        ffma2(acc[16], Av0.x, W); ffma2(acc[17], Av0.y, W);
        ffma2(acc[18], Av1.x, W); ffma2(acc[19], Av1.y, W);
        W = pack2(w1.y);
        ffma2(acc[20], Av0.x, W); ffma2(acc[21], Av0.y, W);
        ffma2(acc[22], Av1.x, W); ffma2(acc[23], Av1.y, W);
        W = pack2(w1.z);
        ffma2(acc[24], Av0.x, W); ffma2(acc[25], Av0.y, W);
        ffma2(acc[26], Av1.x, W); ffma2(acc[27], Av1.y, W);
        W = pack2(w1.w);
        ffma2(acc[28], Av0.x, W); ffma2(acc[29], Av0.y, W);
        ffma2(acc[30], Av1.x, W); ffma2(acc[31], Av1.y, W);
        ap += 16 * B_;
        wp += 16 * 16;
    }
}

// ---- one LSTM step for this CTA's 4 h-columns (16 gate rows) ----
// nA/nB are segment lengths in 16-k blocks. srcB==nullptr -> zero h state.
__device__ __forceinline__ void lstm_step3(
    const float* __restrict__ Wt, const float* __restrict__ bias,
    ull* __restrict__ red,
    const float* __restrict__ srcA, int nA,
    const float* __restrict__ srcB, int nB,
    float* __restrict__ hout, float2 &cs)
{
    const int tid = threadIdx.x;
    const int bo = tid & 7;
    const int rg = (tid >> 3) & 1;
    const int kq = (tid >> 4) & 1;
    const int w  = tid >> 5;
    const int koff = w * 2 + kq;

    ull acc[32];
#pragma unroll
    for (int i = 0; i < 32; i++) acc[i] = 0ull;

    gate_gemm_seg(acc, srcA, Wt, nA, koff, bo, rg);
    if (srcB)
        gate_gemm_seg(acc, srcB, Wt + nA * 16 * 16, nB, koff, bo, rg);

    // collapse the in-warp kq split (lane bit 4)
#pragma unroll
    for (int i = 0; i < 32; i++) acc[i] = addx2(acc[i], shflx16(acc[i]));

    __syncthreads();   // previous activation finished reading red
    {
        // kq=0 writes rows rg*8+0..3, kq=1 writes rows rg*8+4..7
        ull* rw = red + w * 512 + (rg * 8 + kq * 4) * 32 + bo * 4;
#pragma unroll
        for (int r = 0; r < 4; r++) {
            int ar = kq * 4 + r;
            ulonglong2* d = (ulonglong2*)(rw + r * 32);
            d[0] = make_ulonglong2(acc[ar * 4 + 0], acc[ar * 4 + 1]);
            d[1] = make_ulonglong2(acc[ar * 4 + 2], acc[ar * 4 + 3]);
        }
    }
    __syncthreads();

    // activation: thread (c4, bp) owns h-col c4, batches {2bp, 2bp+1}
    if (tid < 128) {
        const int c4 = tid >> 5, bp = tid & 31;
        ull s[4];
#pragma unroll
        for (int g = 0; g < 4; g++) {
            const ull* rr = red + (g * 4 + c4) * 32 + bp;
            ull v = rr[0];
#pragma unroll
            for (int ww = 1; ww < 8; ww++) v = addx2(v, rr[ww * 512]);
            s[g] = addx2(v, pack2(bias[g * 4 + c4]));
        }
        float i0 = sigm(lo2(s[0])), i1 = sigm(hi2(s[0]));
        float f0 = sigm(lo2(s[1])), f1 = sigm(hi2(s[1]));
        float g0 = tanh_(lo2(s[2])), g1 = tanh_(hi2(s[2]));
        float o0 = sigm(lo2(s[3])), o1 = sigm(hi2(s[3]));
        cs.x = f0 * cs.x + i0 * g0;
        cs.y = f1 * cs.y + i1 * g1;
        *(float2*)(hout + c4 * B_ + 2 * bp) =
            make_float2(o0 * tanh_(cs.x), o1 * tanh_(cs.y));
    }
}

// ---------------------------------------------------------------------------
// Mega kernel: transpose + both LSTM layers (pipelined) + FC, one launch.
__global__ void __launch_bounds__(NT, 1) mega_kernel(
    const float* __restrict__ x,
    const float* __restrict__ W_ih0, const float* __restrict__ W_hh0,
    const float* __restrict__ b_ih0, const float* __restrict__ b_hh0,
    const float* __restrict__ W_ih1, const float* __restrict__ W_hh1,
    const float* __restrict__ b_ih1, const float* __restrict__ b_hh1,
    const float* __restrict__ Wfc,  const float* __restrict__ bfc,
    float* __restrict__ out)
{
    extern __shared__ float sm[];
    float* Wt0   = sm;                 // [640][16]  = 10240 floats
    float* Wt1   = sm + 10240;         // [1024][16] = 16384 floats
    float* bias0 = sm + 26624;         // 16
    float* bias1 = sm + 26640;         // 16
    ull*   red   = (ull*)(sm + 26656); // 8 warps * 512 ull = 32768 B

    const int tid = threadIdx.x;
    const int hj0 = blockIdx.x * 4;

    unsigned sense = 0;
    if (tid == 0) sense = *(volatile unsigned*)&g_bar_sense;

    // ---- transpose phase: x[b][t][i] -> g_xT[t][i][b] (tile in Wt1 region)
    {
        float (*tile)[I_ + 1] = (float (*)[I_ + 1])Wt1;   // 64 x 129 = 8256
        for (int t = blockIdx.x; t < T_; t += GRID0) {
            __syncthreads();
            for (int idx = tid; idx < B_ * I_; idx += NT) {
                int b = idx >> 7, i = idx & 127;
                tile[b][i] = x[(b * T_ + t) * I_ + i];
            }
            __syncthreads();
            for (int idx = tid; idx < B_ * I_; idx += NT) {
                int b = idx & 63, i = idx >> 6;
                g_xT[t * I_ * B_ + i * B_ + b] = tile[b][i];
            }
        }
    }
    gridbar(sense);

    // ---- transposed weight slices: Wt[k][r], r = gate*4 + c
    for (int idx = tid; idx < 640 * 16; idx += NT) {
        int k = idx >> 4, r = idx & 15;
        int grow = (r >> 2) * H_ + hj0 + (r & 3);
        Wt0[idx] = (k < I_) ? W_ih0[grow * I_ + k]
                            : W_hh0[grow * H_ + (k - I_)];
    }
    for (int idx = tid; idx < 1024 * 16; idx += NT) {
        int k = idx >> 4, r = idx & 15;
        int grow = (r >> 2) * H_ + hj0 + (r & 3);
        Wt1[idx] = (k < H_) ? W_ih1[grow * H_ + k]
                            : W_hh1[grow * H_ + (k - H_)];
    }
    if (tid < 16) {
        int grow = (tid >> 2) * H_ + hj0 + (tid & 3);
        bias0[tid] = b_ih0[grow] + b_hh0[grow];
        bias1[tid] = b_ih1[grow] + b_hh1[grow];
    }
    __syncthreads();

    // ---- main pipelined loop: layer0 at t=k, layer1 at s=k-1
    float2 c0 = make_float2(0.f, 0.f), c1 = make_float2(0.f, 0.f);
    for (int k = 0; k <= T_; ++k) {
        if (k < T_) {
            const float* sB = (k > 0) ? (g_h0buf + ((k - 1) & 1) * H_ * B_)
                                      : (const float*)0;
            lstm_step3(Wt0, bias0, red,
                       g_xT + k * I_ * B_, I_ / 16, sB, H_ / 16,
                       g_h0buf + (k & 1) * H_ * B_ + hj0 * B_, c0);
        }
        if (k >= 1) {
            int s = k - 1;
            const float* sB = (s > 0) ? (g_h1 + (s - 1) * H_ * B_)
                                      : (const float*)0;
            lstm_step3(Wt1, bias1, red,
                       g_h0buf + (s & 1) * H_ * B_, H_ / 16, sB, H_ / 16,
                       g_h1 + s * H_ * B_ + hj0 * B_, c1);
        }
        gridbar(sense);
    }

    // ---- FC phase: out[b][t][o] = sum_h h1[t][h][b] * Wfc[o][h] + bfc[o]
    {
        float* w_s = sm;                  // 128 x 65 = 8320
        float* h_s = sm + 8320;           // 64 x 64  = 4096
        float* o_s = sm + 12416;          // 64 x 128 = 8192
        const int ot = tid & 15;          // o = ot + j*16
        const int bt = tid >> 4;          // 0..15 -> batches bt*4 .. bt*4+3

        for (int t = blockIdx.x; t < T_; t += GRID0) {
            ull acc[16];
#pragma unroll
            for (int i = 0; i < 16; i++) acc[i] = 0ull;

            for (int kb = 0; kb < H_; kb += 64) {
                __syncthreads();
                for (int idx = tid; idx < O_ * 64; idx += NT) {
                    int o = idx >> 6, kk = idx & 63;
                    w_s[o * 65 + kk] = Wfc[o * H_ + kb + kk];
                }
                for (int idx = tid; idx < 64 * B_; idx += NT) {
                    h_s[idx] = g_h1[(t * H_ + kb) * B_ + idx];
                }
                __syncthreads();
#pragma unroll 4
                for (int kk = 0; kk < 64; kk++) {
                    ulonglong2 A = *(const ulonglong2*)(h_s + kk * B_ + bt * 4);
#pragma unroll
                    for (int j = 0; j < 8; j++) {
                        ull w = pack2(w_s[(ot + j * 16) * 65 + kk]);
                        ffma2(acc[j * 2 + 0], A.x, w);
                        ffma2(acc[j * 2 + 1], A.y, w);
                    }
                }
            }
            __syncthreads();
#pragma unroll
            for (int j = 0; j < 8; j++) {
                int o = ot + j * 16;
                o_s[(bt * 4 + 0) * O_ + o] = lo2(acc[j * 2 + 0]);
                o_s[(bt * 4 + 1) * O_ + o] = hi2(acc[j * 2 + 0]);
                o_s[(bt * 4 + 2) * O_ + o] = lo2(acc[j * 2 + 1]);
                o_s[(bt * 4 + 3) * O_ + o] = hi2(acc[j * 2 + 1]);
            }
            __syncthreads();
            for (int idx = tid; idx < B_ * O_; idx += NT) {
                int b = idx >> 7, o = idx & 127;
                out[(b * T_ + t) * O_ + o] = o_s[idx] + __ldg(&bfc[o]);
            }
        }
    }
}

// ---------------------------------------------------------------------------
extern "C" void kernel_launch(void* const* d_in, const int* in_sizes, int n_in,
                              void* d_out, int out_size) {
    const float* x     = (const float*)d_in[0];
    const float* W_ih0 = (const float*)d_in[1];
    const float* W_hh0 = (const float*)d_in[2];
    const float* b_ih0 = (const float*)d_in[3];
    const float* b_hh0 = (const float*)d_in[4];
    const float* W_ih1 = (const float*)d_in[5];
    const float* W_hh1 = (const float*)d_in[6];
    const float* b_ih1 = (const float*)d_in[7];
    const float* b_hh1 = (const float*)d_in[8];
    const float* W_fc  = (const float*)d_in[9];
    const float* b_fc  = (const float*)d_in[10];
    float* out = (float*)d_out;

    size_t smem = (size_t)(26656 * 4 + 32768);   // 139392 B
    cudaFuncSetAttribute(mega_kernel, cudaFuncAttributeMaxDynamicSharedMemorySize, (int)smem);

    mega_kernel<<<GRID0, NT, smem>>>(x, W_ih0, W_hh0, b_ih0, b_hh0,
                                     W_ih1, W_hh1, b_ih1, b_hh1,
                                     W_fc, b_fc, out);
}

// round 9
// speedup vs baseline: 2.6590x; 1.5781x over previous
#include <cuda_runtime.h>
#include <math.h>

#define B_ 64
#define T_ 1024
#define I_ 128
#define H_ 512
#define O_ 128
#define GRID0 128
#define NT 512

typedef unsigned long long ull;

// ---- scratch (device globals: allocation-free) ----
__device__ float g_xT[T_ * I_ * B_];      // x transposed: [t][i][b]
__device__ float g_h0buf[2 * H_ * B_];    // layer0 h double buffer
__device__ float g_h1[T_ * H_ * B_];      // layer1 h history: [t][h][b]
__device__ unsigned g_bar_count;
__device__ unsigned g_bar_sense;

// ---- packed f32x2 helpers ----
__device__ __forceinline__ ull pack2(float x) {
    ull r; unsigned u = __float_as_uint(x);
    asm("mov.b64 %0, {%1, %1};" : "=l"(r) : "r"(u));
    return r;
}
__device__ __forceinline__ void ffma2(ull &acc, ull a, ull w) {
    asm("fma.rn.f32x2 %0, %1, %2, %0;" : "+l"(acc) : "l"(a), "l"(w));
}
__device__ __forceinline__ ull addx2(ull a, ull b) {
    ull r;
    asm("add.rn.f32x2 %0, %1, %2;" : "=l"(r) : "l"(a), "l"(b));
    return r;
}
__device__ __forceinline__ float lo2(ull v) { return __uint_as_float((unsigned)v); }
__device__ __forceinline__ float hi2(ull v) { return __uint_as_float((unsigned)(v >> 32)); }

__device__ __forceinline__ float sigm(float x) {
    return __fdividef(1.f, 1.f + __expf(-x));
}
__device__ __forceinline__ float tanh_(float x) {
    return __fdividef(2.f, 1.f + __expf(-2.f * x)) - 1.f;
}

// ---- grid barrier (identical to passing R8 kernel) ----
__device__ __forceinline__ void gridbar(unsigned &sense) {
    __syncthreads();
    if (threadIdx.x == 0) {
        unsigned s = sense ^ 1u;
        sense = s;
        unsigned old;
        asm volatile("atom.release.gpu.global.add.u32 %0, [%1], %2;"
                     : "=r"(old) : "l"(&g_bar_count), "r"(1u));
        if (old == GRID0 - 1u) {
            g_bar_count = 0u;
            asm volatile("st.release.gpu.global.u32 [%0], %1;"
                         :: "l"(&g_bar_sense), "r"(s));
        } else {
            unsigned v;
            do {
                asm volatile("ld.acquire.gpu.global.u32 %0, [%1];"
                             : "=r"(v) : "l"(&g_bar_sense));
            } while (v != s);
        }
    }
    __syncthreads();
}

// ---- gate GEMM over one source segment ----
// Warp w handles k = blk*16 + w. Thread (bo, rg): rows rg*8..+7, batches bo*4..+3.
// acc[r*2+p]: row rg*8+r, batch ull p (batches bo*4+2p, bo*4+2p+1).
__device__ __forceinline__ void gate_gemm_seg(
    ull acc[16], const float* __restrict__ src, const float* __restrict__ Wt,
    int nblk, int w, int bo, int rg)
{
    const float* ap = src + w * B_ + bo * 4;
    const float* wp = Wt + w * 16 + rg * 8;
#pragma unroll 4
    for (int c = 0; c < nblk; c++) {
        ulonglong2 Av = __ldcg((const ulonglong2*)ap);
        float4 w0 = *(const float4*)(wp);
        float4 w1 = *(const float4*)(wp + 4);
        ull W;
        W = pack2(w0.x); ffma2(acc[0],  Av.x, W); ffma2(acc[1],  Av.y, W);
        W = pack2(w0.y); ffma2(acc[2],  Av.x, W); ffma2(acc[3],  Av.y, W);
        W = pack2(w0.z); ffma2(acc[4],  Av.x, W); ffma2(acc[5],  Av.y, W);
        W = pack2(w0.w); ffma2(acc[6],  Av.x, W); ffma2(acc[7],  Av.y, W);
        W = pack2(w1.x); ffma2(acc[8],  Av.x, W); ffma2(acc[9],  Av.y, W);
        W = pack2(w1.y); ffma2(acc[10], Av.x, W); ffma2(acc[11], Av.y, W);
        W = pack2(w1.z); ffma2(acc[12], Av.x, W); ffma2(acc[13], Av.y, W);
        W = pack2(w1.w); ffma2(acc[14], Av.x, W); ffma2(acc[15], Av.y, W);
        ap += 16 * B_;
        wp += 16 * 16;
    }
}

// ---- one LSTM step for this CTA's 4 h-columns (16 gate rows) ----
// nA/nB in 16-k blocks. srcB==nullptr -> zero h state.
__device__ __forceinline__ void lstm_step4(
    const float* __restrict__ Wt, const float* __restrict__ bias,
    ull* __restrict__ red,
    const float* __restrict__ srcA, int nA,
    const float* __restrict__ srcB, int nB,
    float* __restrict__ hout, float2 &cs)
{
    const int tid = threadIdx.x;
    const int bo = tid & 15;
    const int rg = (tid >> 4) & 1;
    const int w  = tid >> 5;

    ull acc[16];
#pragma unroll
    for (int i = 0; i < 16; i++) acc[i] = 0ull;

    gate_gemm_seg(acc, srcA, Wt, nA, w, bo, rg);
    if (srcB)
        gate_gemm_seg(acc, srcB, Wt + nA * 16 * 16, nB, w, bo, rg);

    __syncthreads();   // previous activation finished reading red
    {
        ull* rw = red + w * 512 + (rg * 8) * 32 + bo * 2;
#pragma unroll
        for (int r = 0; r < 8; r++) {
            *(ulonglong2*)(rw + r * 32) =
                make_ulonglong2(acc[r * 2 + 0], acc[r * 2 + 1]);
        }
    }
    __syncthreads();

    // activation: thread (c4, bp) owns h-col c4, batches {2bp, 2bp+1}
    if (tid < 128) {
        const int c4 = tid >> 5, bp = tid & 31;
        ull s[4];
#pragma unroll
        for (int g = 0; g < 4; g++) {
            const ull* rr = red + (g * 4 + c4) * 32 + bp;
            ull v = rr[0];
#pragma unroll
            for (int ww = 1; ww < 16; ww++) v = addx2(v, rr[ww * 512]);
            s[g] = addx2(v, pack2(bias[g * 4 + c4]));
        }
        float i0 = sigm(lo2(s[0])), i1 = sigm(hi2(s[0]));
        float f0 = sigm(lo2(s[1])), f1 = sigm(hi2(s[1]));
        float g0 = tanh_(lo2(s[2])), g1 = tanh_(hi2(s[2]));
        float o0 = sigm(lo2(s[3])), o1 = sigm(hi2(s[3]));
        cs.x = f0 * cs.x + i0 * g0;
        cs.y = f1 * cs.y + i1 * g1;
        *(float2*)(hout + c4 * B_ + 2 * bp) =
            make_float2(o0 * tanh_(cs.x), o1 * tanh_(cs.y));
    }
}

// ---------------------------------------------------------------------------
// Mega kernel: transpose + both LSTM layers (pipelined) + FC, one launch.
__global__ void __launch_bounds__(NT, 1) mega_kernel(
    const float* __restrict__ x,
    const float* __restrict__ W_ih0, const float* __restrict__ W_hh0,
    const float* __restrict__ b_ih0, const float* __restrict__ b_hh0,
    const float* __restrict__ W_ih1, const float* __restrict__ W_hh1,
    const float* __restrict__ b_ih1, const float* __restrict__ b_hh1,
    const float* __restrict__ Wfc,  const float* __restrict__ bfc,
    float* __restrict__ out)
{
    extern __shared__ float sm[];
    float* Wt0   = sm;                 // [640][16]  = 10240 floats
    float* Wt1   = sm + 10240;         // [1024][16] = 16384 floats
    float* bias0 = sm + 26624;         // 16
    float* bias1 = sm + 26640;         // 16
    ull*   red   = (ull*)(sm + 26656); // 16 warps * 512 ull = 65536 B

    const int tid = threadIdx.x;
    const int hj0 = blockIdx.x * 4;

    unsigned sense = 0;
    if (tid == 0) sense = *(volatile unsigned*)&g_bar_sense;

    // ---- transpose phase: x[b][t][i] -> g_xT[t][i][b] (tile in Wt1 region)
    {
        float (*tile)[I_ + 1] = (float (*)[I_ + 1])Wt1;   // 64 x 129 = 8256
        for (int t = blockIdx.x; t < T_; t += GRID0) {
            __syncthreads();
            for (int idx = tid; idx < B_ * I_; idx += NT) {
                int b = idx >> 7, i = idx & 127;
                tile[b][i] = x[(b * T_ + t) * I_ + i];
            }
            __syncthreads();
            for (int idx = tid; idx < B_ * I_; idx += NT) {
                int b = idx & 63, i = idx >> 6;
                g_xT[t * I_ * B_ + i * B_ + b] = tile[b][i];
            }
        }
    }
    gridbar(sense);

    // ---- transposed weight slices: Wt[k][r], r = gate*4 + c
    for (int idx = tid; idx < 640 * 16; idx += NT) {
        int k = idx >> 4, r = idx & 15;
        int grow = (r >> 2) * H_ + hj0 + (r & 3);
        Wt0[idx] = (k < I_) ? W_ih0[grow * I_ + k]
                            : W_hh0[grow * H_ + (k - I_)];
    }
    for (int idx = tid; idx < 1024 * 16; idx += NT) {
        int k = idx >> 4, r = idx & 15;
        int grow = (r >> 2) * H_ + hj0 + (r & 3);
        Wt1[idx] = (k < H_) ? W_ih1[grow * H_ + k]
                            : W_hh1[grow * H_ + (k - H_)];
    }
    if (tid < 16) {
        int grow = (tid >> 2) * H_ + hj0 + (tid & 3);
        bias0[tid] = b_ih0[grow] + b_hh0[grow];
        bias1[tid] = b_ih1[grow] + b_hh1[grow];
    }
    __syncthreads();

    // ---- main pipelined loop: layer0 at t=k, layer1 at s=k-1
    float2 c0 = make_float2(0.f, 0.f), c1 = make_float2(0.f, 0.f);
    for (int k = 0; k <= T_; ++k) {
        if (k < T_) {
            const float* sB = (k > 0) ? (g_h0buf + ((k - 1) & 1) * H_ * B_)
                                      : (const float*)0;
            lstm_step4(Wt0, bias0, red,
                       g_xT + k * I_ * B_, I_ / 16, sB, H_ / 16,
                       g_h0buf + (k & 1) * H_ * B_ + hj0 * B_, c0);
        }
        if (k >= 1) {
            int s = k - 1;
            const float* sB = (s > 0) ? (g_h1 + (s - 1) * H_ * B_)
                                      : (const float*)0;
            lstm_step4(Wt1, bias1, red,
                       g_h0buf + (s & 1) * H_ * B_, H_ / 16, sB, H_ / 16,
                       g_h1 + s * H_ * B_ + hj0 * B_, c1);
        }
        gridbar(sense);
    }

    // ---- FC phase: out[b][t][o] = sum_h h1[t][h][b] * Wfc[o][h] + bfc[o]
    {
        float* w_s = sm;                  // 128 x 65 = 8320
        float* h_s = sm + 8320;           // 64 x 64  = 4096
        float* o_s = sm + 12416;          // 64 x 128 = 8192
        const int ot = tid & 15;          // o = ot + j*16
        const int bt = (tid >> 4) & 15;   // batches bt*4 .. bt*4+3 (tid<256 only)

        for (int t = blockIdx.x; t < T_; t += GRID0) {
            ull acc[16];
#pragma unroll
            for (int i = 0; i < 16; i++) acc[i] = 0ull;

            for (int kb = 0; kb < H_; kb += 64) {
                __syncthreads();
                for (int idx = tid; idx < O_ * 64; idx += NT) {
                    int o = idx >> 6, kk = idx & 63;
                    w_s[o * 65 + kk] = Wfc[o * H_ + kb + kk];
                }
                for (int idx = tid; idx < 64 * B_; idx += NT) {
                    h_s[idx] = g_h1[(t * H_ + kb) * B_ + idx];
                }
                __syncthreads();
                if (tid < 256) {
#pragma unroll 4
                    for (int kk = 0; kk < 64; kk++) {
                        ulonglong2 A = *(const ulonglong2*)(h_s + kk * B_ + bt * 4);
#pragma unroll
                        for (int j = 0; j < 8; j++) {
                            ull w = pack2(w_s[(ot + j * 16) * 65 + kk]);
                            ffma2(acc[j * 2 + 0], A.x, w);
                            ffma2(acc[j * 2 + 1], A.y, w);
                        }
                    }
                }
            }
            __syncthreads();
            if (tid < 256) {
#pragma unroll
                for (int j = 0; j < 8; j++) {
                    int o = ot + j * 16;
                    o_s[(bt * 4 + 0) * O_ + o] = lo2(acc[j * 2 + 0]);
                    o_s[(bt * 4 + 1) * O_ + o] = hi2(acc[j * 2 + 0]);
                    o_s[(bt * 4 + 2) * O_ + o] = lo2(acc[j * 2 + 1]);
                    o_s[(bt * 4 + 3) * O_ + o] = hi2(acc[j * 2 + 1]);
                }
            }
            __syncthreads();
            for (int idx = tid; idx < B_ * O_; idx += NT) {
                int b = idx >> 7, o = idx & 127;
                out[(b * T_ + t) * O_ + o] = o_s[idx] + __ldg(&bfc[o]);
            }
        }
    }
}

// ---------------------------------------------------------------------------
extern "C" void kernel_launch(void* const* d_in, const int* in_sizes, int n_in,
                              void* d_out, int out_size) {
    const float* x     = (const float*)d_in[0];
    const float* W_ih0 = (const float*)d_in[1];
    const float* W_hh0 = (const float*)d_in[2];
    const float* b_ih0 = (const float*)d_in[3];
    const float* b_hh0 = (const float*)d_in[4];
    const float* W_ih1 = (const float*)d_in[5];
    const float* W_hh1 = (const float*)d_in[6];
    const float* b_ih1 = (const float*)d_in[7];
    const float* b_hh1 = (const float*)d_in[8];
    const float* W_fc  = (const float*)d_in[9];
    const float* b_fc  = (const float*)d_in[10];
    float* out = (float*)d_out;

    size_t smem = (size_t)(26656 * 4 + 65536);   // 172160 B
    cudaFuncSetAttribute(mega_kernel, cudaFuncAttributeMaxDynamicSharedMemorySize, (int)smem);

    mega_kernel<<<GRID0, NT, smem>>>(x, W_ih0, W_hh0, b_ih0, b_hh0,
                                     W_ih1, W_hh1, b_ih1, b_hh1,
                                     W_fc, b_fc, out);
}

// round 10
// speedup vs baseline: 2.9175x; 1.0972x over previous
#include <cuda_runtime.h>
#include <math.h>

#define B_ 64
#define T_ 1024
#define I_ 128
#define H_ 512
#define O_ 128
#define GRID0 128
#define NT 512

typedef unsigned long long ull;

// ---- scratch (device globals: allocation-free) ----
__device__ float g_xT[T_ * I_ * B_];      // x transposed: [t][i][b]
__device__ float g_h0buf[2 * H_ * B_];    // layer0 h double buffer
__device__ float g_h1[T_ * H_ * B_];      // layer1 h history: [t][h][b]
__device__ unsigned g_bar_count;
__device__ unsigned g_bar_sense;

// ---- packed f32x2 helpers ----
__device__ __forceinline__ ull pack2(float x) {
    ull r; unsigned u = __float_as_uint(x);
    asm("mov.b64 %0, {%1, %1};" : "=l"(r) : "r"(u));
    return r;
}
__device__ __forceinline__ ull pack_ab(float a, float b) {
    ull r;
    asm("mov.b64 %0, {%1, %2};" : "=l"(r)
        : "r"(__float_as_uint(a)), "r"(__float_as_uint(b)));
    return r;
}
__device__ __forceinline__ void ffma2(ull &acc, ull a, ull w) {
    asm("fma.rn.f32x2 %0, %1, %2, %0;" : "+l"(acc) : "l"(a), "l"(w));
}
__device__ __forceinline__ ull addx2(ull a, ull b) {
    ull r;
    asm("add.rn.f32x2 %0, %1, %2;" : "=l"(r) : "l"(a), "l"(b));
    return r;
}
__device__ __forceinline__ float lo2(ull v) { return __uint_as_float((unsigned)v); }
__device__ __forceinline__ float hi2(ull v) { return __uint_as_float((unsigned)(v >> 32)); }

__device__ __forceinline__ float sigm(float x) {
    return __fdividef(1.f, 1.f + __expf(-x));
}
__device__ __forceinline__ float tanh_(float x) {
    return __fdividef(2.f, 1.f + __expf(-2.f * x)) - 1.f;
}

// ---- grid barrier (identical to passing R8/R9 kernel) ----
__device__ __forceinline__ void gridbar(unsigned &sense) {
    __syncthreads();
    if (threadIdx.x == 0) {
        unsigned s = sense ^ 1u;
        sense = s;
        unsigned old;
        asm volatile("atom.release.gpu.global.add.u32 %0, [%1], %2;"
                     : "=r"(old) : "l"(&g_bar_count), "r"(1u));
        if (old == GRID0 - 1u) {
            g_bar_count = 0u;
            asm volatile("st.release.gpu.global.u32 [%0], %1;"
                         :: "l"(&g_bar_sense), "r"(s));
        } else {
            unsigned v;
            do {
                asm volatile("ld.acquire.gpu.global.u32 %0, [%1];"
                             : "=r"(v) : "l"(&g_bar_sense));
            } while (v != s);
        }
    }
    __syncthreads();
}

// ---- Y-form gate GEMM over one source segment ----
// Warp w handles k = blk*16 + w. Thread (bo, rg): rows rg*8..rg*8+7 as 4 row-pair
// lanes, batches bo*4..bo*4+3. acc[rpl*4 + b] = f32x2(row rg*8+2rpl, +2rpl+1) @ batch bo*4+b.
__device__ __forceinline__ void gemmY(
    ull acc[16], const float* __restrict__ src, const float* __restrict__ Wt,
    int nblk, int w, int bo, int rg)
{
    const float* ap = src + w * B_ + bo * 4;
    const float* wp = Wt + w * 16 + rg * 8;
#pragma unroll 8
    for (int c = 0; c < nblk; c++) {
        float4 A = __ldcg((const float4*)ap);
        ulonglong2 W01 = *(const ulonglong2*)wp;        // row-pairs 0,1
        ulonglong2 W23 = *(const ulonglong2*)(wp + 4);  // row-pairs 2,3
        ull A0 = pack2(A.x), A1 = pack2(A.y), A2 = pack2(A.z), A3 = pack2(A.w);
        ffma2(acc[0],  A0, W01.x); ffma2(acc[1],  A1, W01.x);
        ffma2(acc[2],  A2, W01.x); ffma2(acc[3],  A3, W01.x);
        ffma2(acc[4],  A0, W01.y); ffma2(acc[5],  A1, W01.y);
        ffma2(acc[6],  A2, W01.y); ffma2(acc[7],  A3, W01.y);
        ffma2(acc[8],  A0, W23.x); ffma2(acc[9],  A1, W23.x);
        ffma2(acc[10], A2, W23.x); ffma2(acc[11], A3, W23.x);
        ffma2(acc[12], A0, W23.y); ffma2(acc[13], A1, W23.y);
        ffma2(acc[14], A2, W23.y); ffma2(acc[15], A3, W23.y);
        ap += 16 * B_;
        wp += 16 * 16;
    }
}

// ---- one LSTM step for this CTA's 4 h-columns (16 gate rows) ----
// red layout: [w][rp][b] = w*512 + rp*64 + b   (rp = global row-pair 0..7)
// gs  layout: [r][b] floats, r = gate*4 + c4 (16 x 64)
__device__ __forceinline__ void lstm_step5(
    const float* __restrict__ Wt, const float* __restrict__ bias,
    ull* __restrict__ red, float* __restrict__ gs,
    const float* __restrict__ srcA, int nA,
    const float* __restrict__ srcB, int nB,
    float* __restrict__ hout, float2 &cs)
{
    const int tid = threadIdx.x;
    const int bo = tid & 15;
    const int rg = (tid >> 4) & 1;
    const int w  = tid >> 5;

    ull acc[16];
#pragma unroll
    for (int i = 0; i < 16; i++) acc[i] = 0ull;

    gemmY(acc, srcA, Wt, nA, w, bo, rg);
    if (srcB)
        gemmY(acc, srcB, Wt + nA * 16 * 16, nB, w, bo, rg);

    __syncthreads();   // previous readers of red/gs are done
    {
        ull* rw = red + w * 512 + (rg * 4) * 64 + bo * 4;
#pragma unroll
        for (int rpl = 0; rpl < 4; rpl++) {
            *(ulonglong2*)(rw + rpl * 64)     =
                make_ulonglong2(acc[rpl * 4 + 0], acc[rpl * 4 + 1]);
            *(ulonglong2*)(rw + rpl * 64 + 2) =
                make_ulonglong2(acc[rpl * 4 + 2], acc[rpl * 4 + 3]);
        }
    }
    __syncthreads();

    // stage 1: all 512 threads; unit = (row-pair rp, batch b)
    {
        const int rp = tid >> 6, b = tid & 63;
        const ull* rr = red + rp * 64 + b;
        ull v = rr[0];
#pragma unroll
        for (int ww = 1; ww < 16; ww++) v = addx2(v, rr[ww * 512]);
        float2 bb = *(const float2*)(bias + 2 * rp);
        v = addx2(v, pack_ab(bb.x, bb.y));
        gs[(2 * rp) * 64 + b]     = lo2(v);
        gs[(2 * rp + 1) * 64 + b] = hi2(v);
    }
    __syncthreads();

    // stage 2: nonlinearity; thread (c4, bp) owns h-col c4, batches {2bp, 2bp+1}
    if (tid < 128) {
        const int c4 = tid >> 5, bp = tid & 31;
        float2 xi = *(const float2*)(gs + (0  + c4) * 64 + 2 * bp);
        float2 xf = *(const float2*)(gs + (4  + c4) * 64 + 2 * bp);
        float2 xg = *(const float2*)(gs + (8  + c4) * 64 + 2 * bp);
        float2 xo = *(const float2*)(gs + (12 + c4) * 64 + 2 * bp);
        float i0 = sigm(xi.x), i1 = sigm(xi.y);
        float f0 = sigm(xf.x), f1 = sigm(xf.y);
        float g0 = tanh_(xg.x), g1 = tanh_(xg.y);
        float o0 = sigm(xo.x), o1 = sigm(xo.y);
        cs.x = f0 * cs.x + i0 * g0;
        cs.y = f1 * cs.y + i1 * g1;
        *(float2*)(hout + c4 * B_ + 2 * bp) =
            make_float2(o0 * tanh_(cs.x), o1 * tanh_(cs.y));
    }
}

// ---------------------------------------------------------------------------
// Mega kernel: transpose + both LSTM layers (pipelined) + FC, one launch.
__global__ void __launch_bounds__(NT, 1) mega_kernel(
    const float* __restrict__ x,
    const float* __restrict__ W_ih0, const float* __restrict__ W_hh0,
    const float* __restrict__ b_ih0, const float* __restrict__ b_hh0,
    const float* __restrict__ W_ih1, const float* __restrict__ W_hh1,
    const float* __restrict__ b_ih1, const float* __restrict__ b_hh1,
    const float* __restrict__ Wfc,  const float* __restrict__ bfc,
    float* __restrict__ out)
{
    extern __shared__ float sm[];
    float* Wt0   = sm;                 // [640][16]  = 10240 floats
    float* Wt1   = sm + 10240;         // [1024][16] = 16384 floats
    float* bias0 = sm + 26624;         // 16
    float* bias1 = sm + 26640;         // 16
    float* gs    = sm + 26656;         // 16 x 64    = 1024 floats
    ull*   red   = (ull*)(sm + 27680); // 16 warps * 512 ull = 65536 B

    const int tid = threadIdx.x;
    const int hj0 = blockIdx.x * 4;

    unsigned sense = 0;
    if (tid == 0) sense = *(volatile unsigned*)&g_bar_sense;

    // ---- transpose phase: x[b][t][i] -> g_xT[t][i][b] (tile in Wt1 region)
    {
        float (*tile)[I_ + 1] = (float (*)[I_ + 1])Wt1;   // 64 x 129 = 8256
        for (int t = blockIdx.x; t < T_; t += GRID0) {
            __syncthreads();
            for (int idx = tid; idx < B_ * I_; idx += NT) {
                int b = idx >> 7, i = idx & 127;
                tile[b][i] = x[(b * T_ + t) * I_ + i];
            }
            __syncthreads();
            for (int idx = tid; idx < B_ * I_; idx += NT) {
                int b = idx & 63, i = idx >> 6;
                g_xT[t * I_ * B_ + i * B_ + b] = tile[b][i];
            }
        }
    }
    gridbar(sense);

    // ---- transposed weight slices: Wt[k][r], r = gate*4 + c
    for (int idx = tid; idx < 640 * 16; idx += NT) {
        int k = idx >> 4, r = idx & 15;
        int grow = (r >> 2) * H_ + hj0 + (r & 3);
        Wt0[idx] = (k < I_) ? W_ih0[grow * I_ + k]
                            : W_hh0[grow * H_ + (k - I_)];
    }
    for (int idx = tid; idx < 1024 * 16; idx += NT) {
        int k = idx >> 4, r = idx & 15;
        int grow = (r >> 2) * H_ + hj0 + (r & 3);
        Wt1[idx] = (k < H_) ? W_ih1[grow * H_ + k]
                            : W_hh1[grow * H_ + (k - H_)];
    }
    if (tid < 16) {
        int grow = (tid >> 2) * H_ + hj0 + (tid & 3);
        bias0[tid] = b_ih0[grow] + b_hh0[grow];
        bias1[tid] = b_ih1[grow] + b_hh1[grow];
    }
    __syncthreads();

    // ---- main pipelined loop: layer0 at t=k, layer1 at s=k-1
    float2 c0 = make_float2(0.f, 0.f), c1 = make_float2(0.f, 0.f);
    for (int k = 0; k <= T_; ++k) {
        if (k < T_) {
            const float* sB = (k > 0) ? (g_h0buf + ((k - 1) & 1) * H_ * B_)
                                      : (const float*)0;
            lstm_step5(Wt0, bias0, red, gs,
                       g_xT + k * I_ * B_, I_ / 16, sB, H_ / 16,
                       g_h0buf + (k & 1) * H_ * B_ + hj0 * B_, c0);
        }
        if (k >= 1) {
            int s = k - 1;
            const float* sB = (s > 0) ? (g_h1 + (s - 1) * H_ * B_)
                                      : (const float*)0;
            lstm_step5(Wt1, bias1, red, gs,
                       g_h0buf + (s & 1) * H_ * B_, H_ / 16, sB, H_ / 16,
                       g_h1 + s * H_ * B_ + hj0 * B_, c1);
        }
        gridbar(sense);
    }

    // ---- FC phase: out[b][t][o] = sum_h h1[t][h][b] * Wfc[o][h] + bfc[o]
    {
        float* w_s = sm;                  // 128 x 65 = 8320
        float* h_s = sm + 8320;           // 64 x 64  = 4096
        float* o_s = sm + 12416;          // 64 x 128 = 8192
        const int ot = tid & 15;          // o = ot + j*16
        const int bt = (tid >> 4) & 15;   // batches bt*4 .. bt*4+3 (tid<256 only)

        for (int t = blockIdx.x; t < T_; t += GRID0) {
            ull acc[16];
#pragma unroll
            for (int i = 0; i < 16; i++) acc[i] = 0ull;

            for (int kb = 0; kb < H_; kb += 64) {
                __syncthreads();
                for (int idx = tid; idx < O_ * 64; idx += NT) {
                    int o = idx >> 6, kk = idx & 63;
                    w_s[o * 65 + kk] = Wfc[o * H_ + kb + kk];
                }
                for (int idx = tid; idx < 64 * B_; idx += NT) {
                    h_s[idx] = g_h1[(t * H_ + kb) * B_ + idx];
                }
                __syncthreads();
                if (tid < 256) {
#pragma unroll 4
                    for (int kk = 0; kk < 64; kk++) {
                        ulonglong2 A = *(const ulonglong2*)(h_s + kk * B_ + bt * 4);
#pragma unroll
                        for (int j = 0; j < 8; j++) {
                            ull w = pack2(w_s[(ot + j * 16) * 65 + kk]);
                            ffma2(acc[j * 2 + 0], A.x, w);
                            ffma2(acc[j * 2 + 1], A.y, w);
                        }
                    }
                }
            }
            __syncthreads();
            if (tid < 256) {
#pragma unroll
                for (int j = 0; j < 8; j++) {
                    int o = ot + j * 16;
                    o_s[(bt * 4 + 0) * O_ + o] = lo2(acc[j * 2 + 0]);
                    o_s[(bt * 4 + 1) * O_ + o] = hi2(acc[j * 2 + 0]);
                    o_s[(bt * 4 + 2) * O_ + o] = lo2(acc[j * 2 + 1]);
                    o_s[(bt * 4 + 3) * O_ + o] = hi2(acc[j * 2 + 1]);
                }
            }
            __syncthreads();
            for (int idx = tid; idx < B_ * O_; idx += NT) {
                int b = idx >> 7, o = idx & 127;
                out[(b * T_ + t) * O_ + o] = o_s[idx] + __ldg(&bfc[o]);
            }
        }
    }
}

// ---------------------------------------------------------------------------
extern "C" void kernel_launch(void* const* d_in, const int* in_sizes, int n_in,
                              void* d_out, int out_size) {
    const float* x     = (const float*)d_in[0];
    const float* W_ih0 = (const float*)d_in[1];
    const float* W_hh0 = (const float*)d_in[2];
    const float* b_ih0 = (const float*)d_in[3];
    const float* b_hh0 = (const float*)d_in[4];
    const float* W_ih1 = (const float*)d_in[5];
    const float* W_hh1 = (const float*)d_in[6];
    const float* b_ih1 = (const float*)d_in[7];
    const float* b_hh1 = (const float*)d_in[8];
    const float* W_fc  = (const float*)d_in[9];
    const float* b_fc  = (const float*)d_in[10];
    float* out = (float*)d_out;

    size_t smem = (size_t)(27680 * 4 + 65536);   // 176256 B
    cudaFuncSetAttribute(mega_kernel, cudaFuncAttributeMaxDynamicSharedMemorySize, (int)smem);

    mega_kernel<<<GRID0, NT, smem>>>(x, W_ih0, W_hh0, b_ih0, b_hh0,
                                     W_ih1, W_hh1, b_ih1, b_hh1,
                                     W_fc, b_fc, out);
}

// round 11
// speedup vs baseline: 2.9742x; 1.0194x over previous
#include <cuda_runtime.h>
#include <math.h>

#define B_ 64
#define T_ 1024
#define I_ 128
#define H_ 512
#define O_ 128
#define GRID0 128
#define NT 512

typedef unsigned long long ull;

// ---- scratch (device globals: allocation-free) ----
__device__ float g_xT[T_ * I_ * B_];      // x transposed: [t][i][b]
__device__ float g_h0buf[2 * H_ * B_];    // layer0 h double buffer
__device__ float g_h1[T_ * H_ * B_];      // layer1 h history: [t][h][b]
__device__ unsigned g_bar_count;
__device__ unsigned g_bar_sense;

// ---- packed f32x2 helpers ----
__device__ __forceinline__ ull pack2(float x) {
    ull r; unsigned u = __float_as_uint(x);
    asm("mov.b64 %0, {%1, %1};" : "=l"(r) : "r"(u));
    return r;
}
__device__ __forceinline__ ull pack_ab(float a, float b) {
    ull r;
    asm("mov.b64 %0, {%1, %2};" : "=l"(r)
        : "r"(__float_as_uint(a)), "r"(__float_as_uint(b)));
    return r;
}
__device__ __forceinline__ void ffma2(ull &acc, ull a, ull w) {
    asm("fma.rn.f32x2 %0, %1, %2, %0;" : "+l"(acc) : "l"(a), "l"(w));
}
__device__ __forceinline__ ull addx2(ull a, ull b) {
    ull r;
    asm("add.rn.f32x2 %0, %1, %2;" : "=l"(r) : "l"(a), "l"(b));
    return r;
}
__device__ __forceinline__ float lo2(ull v) { return __uint_as_float((unsigned)v); }
__device__ __forceinline__ float hi2(ull v) { return __uint_as_float((unsigned)(v >> 32)); }

__device__ __forceinline__ float sigm(float x) {
    return __fdividef(1.f, 1.f + __expf(-x));
}
__device__ __forceinline__ float tanh_(float x) {
    return __fdividef(2.f, 1.f + __expf(-2.f * x)) - 1.f;
}

// ---- grid barrier (identical to passing R8-R10 kernels) ----
__device__ __forceinline__ void gridbar(unsigned &sense) {
    __syncthreads();
    if (threadIdx.x == 0) {
        unsigned s = sense ^ 1u;
        sense = s;
        unsigned old;
        asm volatile("atom.release.gpu.global.add.u32 %0, [%1], %2;"
                     : "=r"(old) : "l"(&g_bar_count), "r"(1u));
        if (old == GRID0 - 1u) {
            g_bar_count = 0u;
            asm volatile("st.release.gpu.global.u32 [%0], %1;"
                         :: "l"(&g_bar_sense), "r"(s));
        } else {
            unsigned v;
            do {
                asm volatile("ld.acquire.gpu.global.u32 %0, [%1];"
                             : "=r"(v) : "l"(&g_bar_sense));
            } while (v != s);
        }
    }
    __syncthreads();
}

// ---- one 16-k block of Y-form FMAs: A (4 batches) x W (4 row-pairs) ----
__device__ __forceinline__ void fmaBlk(ull acc[16], float4 A, const float* wp) {
    ulonglong2 W01 = *(const ulonglong2*)wp;        // row-pairs 0,1
    ulonglong2 W23 = *(const ulonglong2*)(wp + 4);  // row-pairs 2,3
    ull A0 = pack2(A.x), A1 = pack2(A.y), A2 = pack2(A.z), A3 = pack2(A.w);
    ffma2(acc[0],  A0, W01.x); ffma2(acc[1],  A1, W01.x);
    ffma2(acc[2],  A2, W01.x); ffma2(acc[3],  A3, W01.x);
    ffma2(acc[4],  A0, W01.y); ffma2(acc[5],  A1, W01.y);
    ffma2(acc[6],  A2, W01.y); ffma2(acc[7],  A3, W01.y);
    ffma2(acc[8],  A0, W23.x); ffma2(acc[9],  A1, W23.x);
    ffma2(acc[10], A2, W23.x); ffma2(acc[11], A3, W23.x);
    ffma2(acc[12], A0, W23.y); ffma2(acc[13], A1, W23.y);
    ffma2(acc[14], A2, W23.y); ffma2(acc[15], A3, W23.y);
}

// ---- Y-form gate GEMM over one segment, software-pipelined A prefetch ----
// Warp w handles k = blk*16 + w. Thread (bo, rg): rows rg*8..+7 (4 row-pairs),
// batches bo*4..+3. nblk is even and >= 2 for all call sites.
__device__ __forceinline__ void gemmY(
    ull acc[16], const float* __restrict__ src, const float* __restrict__ Wt,
    int nblk, int w, int bo, int rg)
{
    const float* ap = src + w * B_ + bo * 4;
    const float* wp = Wt + w * 16 + rg * 8;
    const int S = 16 * B_;
    float4 Aa = __ldcg((const float4*)ap);
    float4 Ab = __ldcg((const float4*)(ap + S));
    int c = 0;
    for (; c + 2 < nblk; c += 2) {
        float4 An0 = __ldcg((const float4*)(ap + (c + 2) * S));
        fmaBlk(acc, Aa, wp + c * 256);
        Aa = An0;
        float4 An1 = __ldcg((const float4*)(ap + (c + 3) * S));
        fmaBlk(acc, Ab, wp + (c + 1) * 256);
        Ab = An1;
    }
    fmaBlk(acc, Aa, wp + c * 256);
    fmaBlk(acc, Ab, wp + (c + 1) * 256);
}

// ---------------------------------------------------------------------------
// Mega kernel: transpose + both LSTM layers (pipelined) + FC, one launch.
__global__ void __launch_bounds__(NT, 1) mega_kernel(
    const float* __restrict__ x,
    const float* __restrict__ W_ih0, const float* __restrict__ W_hh0,
    const float* __restrict__ b_ih0, const float* __restrict__ b_hh0,
    const float* __restrict__ W_ih1, const float* __restrict__ W_hh1,
    const float* __restrict__ b_ih1, const float* __restrict__ b_hh1,
    const float* __restrict__ Wfc,  const float* __restrict__ bfc,
    float* __restrict__ out)
{
    extern __shared__ float sm[];
    float* Wt0   = sm;                 // [640][16]  = 10240 floats
    float* Wt1   = sm + 10240;         // [1024][16] = 16384 floats
    float* bias0 = sm + 26624;         // 16
    float* bias1 = sm + 26640;         // 16
    float* gs    = sm + 26656;         // 16 x 64    = 1024 floats
    ull*   red   = (ull*)(sm + 27680); // 16 warps * 512 ull = 65536 B

    const int tid = threadIdx.x;
    const int hj0 = blockIdx.x * 4;
    const int bo = tid & 15;
    const int rg = (tid >> 4) & 1;
    const int w  = tid >> 5;

    unsigned sense = 0;
    if (tid == 0) sense = *(volatile unsigned*)&g_bar_sense;

    // ---- transpose phase: x[b][t][i] -> g_xT[t][i][b] (tile in Wt1 region)
    {
        float (*tile)[I_ + 1] = (float (*)[I_ + 1])Wt1;   // 64 x 129 = 8256
        for (int t = blockIdx.x; t < T_; t += GRID0) {
            __syncthreads();
            for (int idx = tid; idx < B_ * I_; idx += NT) {
                int b = idx >> 7, i = idx & 127;
                tile[b][i] = x[(b * T_ + t) * I_ + i];
            }
            __syncthreads();
            for (int idx = tid; idx < B_ * I_; idx += NT) {
                int b = idx & 63, i = idx >> 6;
                g_xT[t * I_ * B_ + i * B_ + b] = tile[b][i];
            }
        }
    }
    gridbar(sense);

    // ---- transposed weight slices: Wt[k][r], r = gate*4 + c
    for (int idx = tid; idx < 640 * 16; idx += NT) {
        int k = idx >> 4, r = idx & 15;
        int grow = (r >> 2) * H_ + hj0 + (r & 3);
        Wt0[idx] = (k < I_) ? W_ih0[grow * I_ + k]
                            : W_hh0[grow * H_ + (k - I_)];
    }
    for (int idx = tid; idx < 1024 * 16; idx += NT) {
        int k = idx >> 4, r = idx & 15;
        int grow = (r >> 2) * H_ + hj0 + (r & 3);
        Wt1[idx] = (k < H_) ? W_ih1[grow * H_ + k]
                            : W_hh1[grow * H_ + (k - H_)];
    }
    if (tid < 16) {
        int grow = (tid >> 2) * H_ + hj0 + (tid & 3);
        bias0[tid] = b_ih0[grow] + b_hh0[grow];
        bias1[tid] = b_ih1[grow] + b_hh1[grow];
    }
    __syncthreads();

    // ---- main pipelined loop: layer0 at t=k, layer1 at s=k-1.
    // Per layer: GEMM -> dump -> stage1 -> act; layer0's act (128 threads)
    // overlaps the start of layer1's GEMM (no sync between them).
    float2 c0 = make_float2(0.f, 0.f), c1 = make_float2(0.f, 0.f);
    const int rp_u = tid >> 6;          // stage1 unit: row-pair 0..7
    const int b_u  = tid & 63;          //              batch 0..63
    const int c4_a = tid >> 5;          // act unit (tid<128): h-col 0..3
    const int bp_a = tid & 31;          //                      batch-pair

    for (int k = 0; k <= T_; ++k) {
        ull acc[16];

        // ===== layer 0 at t = k =====
        if (k < T_) {
#pragma unroll
            for (int i = 0; i < 16; i++) acc[i] = 0ull;
            gemmY(acc, g_xT + k * I_ * B_, Wt0, I_ / 16, w, bo, rg);
            if (k > 0)
                gemmY(acc, g_h0buf + ((k - 1) & 1) * H_ * B_,
                      Wt0 + (I_ / 16) * 256, H_ / 16, w, bo, rg);
        }
        __syncthreads();                    // red free (prev iter readers done)
        if (k < T_) {
            ull* rw = red + w * 512 + (rg * 4) * 64 + bo * 4;
#pragma unroll
            for (int rpl = 0; rpl < 4; rpl++) {
                *(ulonglong2*)(rw + rpl * 64)     =
                    make_ulonglong2(acc[rpl * 4 + 0], acc[rpl * 4 + 1]);
                *(ulonglong2*)(rw + rpl * 64 + 2) =
                    make_ulonglong2(acc[rpl * 4 + 2], acc[rpl * 4 + 3]);
            }
        }
        __syncthreads();
        if (k < T_) {                       // stage1: 512 threads, 1 unit each
            const ull* rr = red + rp_u * 64 + b_u;
            ull v = rr[0];
#pragma unroll
            for (int ww = 1; ww < 16; ww++) v = addx2(v, rr[ww * 512]);
            float2 bb = *(const float2*)(bias0 + 2 * rp_u);
            v = addx2(v, pack_ab(bb.x, bb.y));
            gs[(2 * rp_u) * 64 + b_u]     = lo2(v);
            gs[(2 * rp_u + 1) * 64 + b_u] = hi2(v);
        }
        __syncthreads();
        if (k < T_ && tid < 128) {          // act0 — overlaps GEMM1 below
            float2 xi = *(const float2*)(gs + (0  + c4_a) * 64 + 2 * bp_a);
            float2 xf = *(const float2*)(gs + (4  + c4_a) * 64 + 2 * bp_a);
            float2 xg = *(const float2*)(gs + (8  + c4_a) * 64 + 2 * bp_a);
            float2 xo = *(const float2*)(gs + (12 + c4_a) * 64 + 2 * bp_a);
            float i0 = sigm(xi.x), i1 = sigm(xi.y);
            float f0 = sigm(xf.x), f1 = sigm(xf.y);
            float g0 = tanh_(xg.x), g1 = tanh_(xg.y);
            float o0 = sigm(xo.x), o1 = sigm(xo.y);
            c0.x = f0 * c0.x + i0 * g0;
            c0.y = f1 * c0.y + i1 * g1;
            *(float2*)(g_h0buf + (k & 1) * H_ * B_ + hj0 * B_
                       + c4_a * B_ + 2 * bp_a) =
                make_float2(o0 * tanh_(c0.x), o1 * tanh_(c0.y));
        }

        // ===== layer 1 at s = k-1 =====
        if (k >= 1) {
            int s = k - 1;
#pragma unroll
            for (int i = 0; i < 16; i++) acc[i] = 0ull;
            gemmY(acc, g_h0buf + (s & 1) * H_ * B_, Wt1, H_ / 16, w, bo, rg);
            if (s > 0)
                gemmY(acc, g_h1 + (s - 1) * H_ * B_,
                      Wt1 + (H_ / 16) * 256, H_ / 16, w, bo, rg);
        }
        __syncthreads();                    // stage1_0 done -> red reusable
        if (k >= 1) {
            ull* rw = red + w * 512 + (rg * 4) * 64 + bo * 4;
#pragma unroll
            for (int rpl = 0; rpl < 4; rpl++) {
                *(ulonglong2*)(rw + rpl * 64)     =
                    make_ulonglong2(acc[rpl * 4 + 0], acc[rpl * 4 + 1]);
                *(ulonglong2*)(rw + rpl * 64 + 2) =
                    make_ulonglong2(acc[rpl * 4 + 2], acc[rpl * 4 + 3]);
            }
        }
        __syncthreads();
        if (k >= 1) {
            const ull* rr = red + rp_u * 64 + b_u;
            ull v = rr[0];
#pragma unroll
            for (int ww = 1; ww < 16; ww++) v = addx2(v, rr[ww * 512]);
            float2 bb = *(const float2*)(bias1 + 2 * rp_u);
            v = addx2(v, pack_ab(bb.x, bb.y));
            gs[(2 * rp_u) * 64 + b_u]     = lo2(v);
            gs[(2 * rp_u + 1) * 64 + b_u] = hi2(v);
        }
        __syncthreads();
        if (k >= 1 && tid < 128) {          // act1 — flows into gridbar sync
            float2 xi = *(const float2*)(gs + (0  + c4_a) * 64 + 2 * bp_a);
            float2 xf = *(const float2*)(gs + (4  + c4_a) * 64 + 2 * bp_a);
            float2 xg = *(const float2*)(gs + (8  + c4_a) * 64 + 2 * bp_a);
            float2 xo = *(const float2*)(gs + (12 + c4_a) * 64 + 2 * bp_a);
            float i0 = sigm(xi.x), i1 = sigm(xi.y);
            float f0 = sigm(xf.x), f1 = sigm(xf.y);
            float g0 = tanh_(xg.x), g1 = tanh_(xg.y);
            float o0 = sigm(xo.x), o1 = sigm(xo.y);
            c1.x = f0 * c1.x + i0 * g0;
            c1.y = f1 * c1.y + i1 * g1;
            *(float2*)(g_h1 + (k - 1) * H_ * B_ + hj0 * B_
                       + c4_a * B_ + 2 * bp_a) =
                make_float2(o0 * tanh_(c1.x), o1 * tanh_(c1.y));
        }
        gridbar(sense);
    }

    // ---- FC phase: out[b][t][o] = sum_h h1[t][h][b] * Wfc[o][h] + bfc[o]
    {
        float* w_s = sm;                  // 128 x 65 = 8320
        float* h_s = sm + 8320;           // 64 x 64  = 4096
        float* o_s = sm + 12416;          // 64 x 128 = 8192
        const int ot = tid & 15;          // o = ot + j*16
        const int bt = (tid >> 4) & 15;   // batches bt*4 .. bt*4+3 (tid<256 only)

        for (int t = blockIdx.x; t < T_; t += GRID0) {
            ull acc[16];
#pragma unroll
            for (int i = 0; i < 16; i++) acc[i] = 0ull;

            for (int kb = 0; kb < H_; kb += 64) {
                __syncthreads();
                for (int idx = tid; idx < O_ * 64; idx += NT) {
                    int o = idx >> 6, kk = idx & 63;
                    w_s[o * 65 + kk] = Wfc[o * H_ + kb + kk];
                }
                for (int idx = tid; idx < 64 * B_; idx += NT) {
                    h_s[idx] = g_h1[(t * H_ + kb) * B_ + idx];
                }
                __syncthreads();
                if (tid < 256) {
#pragma unroll 4
                    for (int kk = 0; kk < 64; kk++) {
                        ulonglong2 A = *(const ulonglong2*)(h_s + kk * B_ + bt * 4);
#pragma unroll
                        for (int j = 0; j < 8; j++) {
                            ull ww = pack2(w_s[(ot + j * 16) * 65 + kk]);
                            ffma2(acc[j * 2 + 0], A.x, ww);
                            ffma2(acc[j * 2 + 1], A.y, ww);
                        }
                    }
                }
            }
            __syncthreads();
            if (tid < 256) {
#pragma unroll
                for (int j = 0; j < 8; j++) {
                    int o = ot + j * 16;
                    o_s[(bt * 4 + 0) * O_ + o] = lo2(acc[j * 2 + 0]);
                    o_s[(bt * 4 + 1) * O_ + o] = hi2(acc[j * 2 + 0]);
                    o_s[(bt * 4 + 2) * O_ + o] = lo2(acc[j * 2 + 1]);
                    o_s[(bt * 4 + 3) * O_ + o] = hi2(acc[j * 2 + 1]);
                }
            }
            __syncthreads();
            for (int idx = tid; idx < B_ * O_; idx += NT) {
                int b = idx >> 7, o = idx & 127;
                out[(b * T_ + t) * O_ + o] = o_s[idx] + __ldg(&bfc[o]);
            }
        }
    }
}

// ---------------------------------------------------------------------------
extern "C" void kernel_launch(void* const* d_in, const int* in_sizes, int n_in,
                              void* d_out, int out_size) {
    const float* x     = (const float*)d_in[0];
    const float* W_ih0 = (const float*)d_in[1];
    const float* W_hh0 = (const float*)d_in[2];
    const float* b_ih0 = (const float*)d_in[3];
    const float* b_hh0 = (const float*)d_in[4];
    const float* W_ih1 = (const float*)d_in[5];
    const float* W_hh1 = (const float*)d_in[6];
    const float* b_ih1 = (const float*)d_in[7];
    const float* b_hh1 = (const float*)d_in[8];
    const float* W_fc  = (const float*)d_in[9];
    const float* b_fc  = (const float*)d_in[10];
    float* out = (float*)d_out;

    size_t smem = (size_t)(27680 * 4 + 65536);   // 176256 B
    cudaFuncSetAttribute(mega_kernel, cudaFuncAttributeMaxDynamicSharedMemorySize, (int)smem);

    mega_kernel<<<GRID0, NT, smem>>>(x, W_ih0, W_hh0, b_ih0, b_hh0,
                                     W_ih1, W_hh1, b_ih1, b_hh1,
                                     W_fc, b_fc, out);
}

// round 12
// speedup vs baseline: 2.9792x; 1.0017x over previous
#include <cuda_runtime.h>
#include <math.h>

#define B_ 64
#define T_ 1024
#define I_ 128
#define H_ 512
#define O_ 128
#define GRID0 128
#define NT 512

typedef unsigned long long ull;

// ---- scratch (device globals: allocation-free) ----
__device__ float g_xT[T_ * I_ * B_];      // x transposed: [t][i][b]
__device__ float g_h0buf[2 * H_ * B_];    // layer0 h double buffer
__device__ float g_h1[T_ * H_ * B_];      // layer1 h history: [t][h][b]
__device__ unsigned g_bar_count;
__device__ unsigned g_bar_sense;

// ---- packed f32x2 helpers ----
__device__ __forceinline__ ull pack2(float x) {
    ull r; unsigned u = __float_as_uint(x);
    asm("mov.b64 %0, {%1, %1};" : "=l"(r) : "r"(u));
    return r;
}
__device__ __forceinline__ ull pack_ab(float a, float b) {
    ull r;
    asm("mov.b64 %0, {%1, %2};" : "=l"(r)
        : "r"(__float_as_uint(a)), "r"(__float_as_uint(b)));
    return r;
}
__device__ __forceinline__ void ffma2(ull &acc, ull a, ull w) {
    asm("fma.rn.f32x2 %0, %1, %2, %0;" : "+l"(acc) : "l"(a), "l"(w));
}
__device__ __forceinline__ ull addx2(ull a, ull b) {
    ull r;
    asm("add.rn.f32x2 %0, %1, %2;" : "=l"(r) : "l"(a), "l"(b));
    return r;
}
__device__ __forceinline__ float lo2(ull v) { return __uint_as_float((unsigned)v); }
__device__ __forceinline__ float hi2(ull v) { return __uint_as_float((unsigned)(v >> 32)); }

__device__ __forceinline__ float sigm(float x) {
    return __fdividef(1.f, 1.f + __expf(-x));
}
__device__ __forceinline__ float tanh_(float x) {
    return __fdividef(2.f, 1.f + __expf(-2.f * x)) - 1.f;
}

// ---- grid barrier (identical to passing R8-R10 kernels) ----
__device__ __forceinline__ void gridbar(unsigned &sense) {
    __syncthreads();
    if (threadIdx.x == 0) {
        unsigned s = sense ^ 1u;
        sense = s;
        unsigned old;
        asm volatile("atom.release.gpu.global.add.u32 %0, [%1], %2;"
                     : "=r"(old) : "l"(&g_bar_count), "r"(1u));
        if (old == GRID0 - 1u) {
            g_bar_count = 0u;
            asm volatile("st.release.gpu.global.u32 [%0], %1;"
                         :: "l"(&g_bar_sense), "r"(s));
        } else {
            unsigned v;
            do {
                asm volatile("ld.acquire.gpu.global.u32 %0, [%1];"
                             : "=r"(v) : "l"(&g_bar_sense));
            } while (v != s);
        }
    }
    __syncthreads();
}

// ---- one 16-k block of Y-form FMAs: A (4 batches) x W (4 row-pairs) ----
__device__ __forceinline__ void fmaBlk(ull acc[16], float4 A, const float* wp) {
    ulonglong2 W01 = *(const ulonglong2*)wp;        // row-pairs 0,1
    ulonglong2 W23 = *(const ulonglong2*)(wp + 4);  // row-pairs 2,3
    ull A0 = pack2(A.x), A1 = pack2(A.y), A2 = pack2(A.z), A3 = pack2(A.w);
    ffma2(acc[0],  A0, W01.x); ffma2(acc[1],  A1, W01.x);
    ffma2(acc[2],  A2, W01.x); ffma2(acc[3],  A3, W01.x);
    ffma2(acc[4],  A0, W01.y); ffma2(acc[5],  A1, W01.y);
    ffma2(acc[6],  A2, W01.y); ffma2(acc[7],  A3, W01.y);
    ffma2(acc[8],  A0, W23.x); ffma2(acc[9],  A1, W23.x);
    ffma2(acc[10], A2, W23.x); ffma2(acc[11], A3, W23.x);
    ffma2(acc[12], A0, W23.y); ffma2(acc[13], A1, W23.y);
    ffma2(acc[14], A2, W23.y); ffma2(acc[15], A3, W23.y);
}

// ---- Y-form gate GEMM over one segment, software-pipelined A prefetch ----
// Warp w handles k = blk*16 + w. Thread (bo, rg): rows rg*8..+7 (4 row-pairs),
// batches bo*4..+3. nblk is even and >= 2 for all call sites.
__device__ __forceinline__ void gemmY(
    ull acc[16], const float* __restrict__ src, const float* __restrict__ Wt,
    int nblk, int w, int bo, int rg)
{
    const float* ap = src + w * B_ + bo * 4;
    const float* wp = Wt + w * 16 + rg * 8;
    const int S = 16 * B_;
    float4 Aa = __ldcg((const float4*)ap);
    float4 Ab = __ldcg((const float4*)(ap + S));
    int c = 0;
    for (; c + 2 < nblk; c += 2) {
        float4 An0 = __ldcg((const float4*)(ap + (c + 2) * S));
        fmaBlk(acc, Aa, wp + c * 256);
        Aa = An0;
        float4 An1 = __ldcg((const float4*)(ap + (c + 3) * S));
        fmaBlk(acc, Ab, wp + (c + 1) * 256);
        Ab = An1;
    }
    fmaBlk(acc, Aa, wp + c * 256);
    fmaBlk(acc, Ab, wp + (c + 1) * 256);
}

// ---------------------------------------------------------------------------
// Mega kernel: transpose + both LSTM layers (pipelined) + FC, one launch.
__global__ void __launch_bounds__(NT, 1) mega_kernel(
    const float* __restrict__ x,
    const float* __restrict__ W_ih0, const float* __restrict__ W_hh0,
    const float* __restrict__ b_ih0, const float* __restrict__ b_hh0,
    const float* __restrict__ W_ih1, const float* __restrict__ W_hh1,
    const float* __restrict__ b_ih1, const float* __restrict__ b_hh1,
    const float* __restrict__ Wfc,  const float* __restrict__ bfc,
    float* __restrict__ out)
{
    extern __shared__ float sm[];
    float* Wt0   = sm;                 // [640][16]  = 10240 floats
    float* Wt1   = sm + 10240;         // [1024][16] = 16384 floats
    float* bias0 = sm + 26624;         // 16
    float* bias1 = sm + 26640;         // 16
    float* gs    = sm + 26656;         // 16 x 64    = 1024 floats
    ull*   red   = (ull*)(sm + 27680); // 16 warps * 512 ull = 65536 B

    const int tid = threadIdx.x;
    const int hj0 = blockIdx.x * 4;
    const int bo = tid & 15;
    const int rg = (tid >> 4) & 1;
    const int w  = tid >> 5;

    unsigned sense = 0;
    if (tid == 0) sense = *(volatile unsigned*)&g_bar_sense;

    // ---- transpose phase: x[b][t][i] -> g_xT[t][i][b] (tile in Wt1 region)
    {
        float (*tile)[I_ + 1] = (float (*)[I_ + 1])Wt1;   // 64 x 129 = 8256
        for (int t = blockIdx.x; t < T_; t += GRID0) {
            __syncthreads();
            for (int idx = tid; idx < B_ * I_; idx += NT) {
                int b = idx >> 7, i = idx & 127;
                tile[b][i] = x[(b * T_ + t) * I_ + i];
            }
            __syncthreads();
            for (int idx = tid; idx < B_ * I_; idx += NT) {
                int b = idx & 63, i = idx >> 6;
                g_xT[t * I_ * B_ + i * B_ + b] = tile[b][i];
            }
        }
    }
    gridbar(sense);

    // ---- transposed weight slices: Wt[k][r], r = gate*4 + c
    for (int idx = tid; idx < 640 * 16; idx += NT) {
        int k = idx >> 4, r = idx & 15;
        int grow = (r >> 2) * H_ + hj0 + (r & 3);
        Wt0[idx] = (k < I_) ? W_ih0[grow * I_ + k]
                            : W_hh0[grow * H_ + (k - I_)];
    }
    for (int idx = tid; idx < 1024 * 16; idx += NT) {
        int k = idx >> 4, r = idx & 15;
        int grow = (r >> 2) * H_ + hj0 + (r & 3);
        Wt1[idx] = (k < H_) ? W_ih1[grow * H_ + k]
                            : W_hh1[grow * H_ + (k - H_)];
    }
    if (tid < 16) {
        int grow = (tid >> 2) * H_ + hj0 + (tid & 3);
        bias0[tid] = b_ih0[grow] + b_hh0[grow];
        bias1[tid] = b_ih1[grow] + b_hh1[grow];
    }
    __syncthreads();

    // ---- main pipelined loop: layer0 at t=k, layer1 at s=k-1.
    // Per layer: GEMM -> dump -> stage1 -> act; layer0's act (128 threads)
    // overlaps the start of layer1's GEMM (no sync between them).
    float2 c0 = make_float2(0.f, 0.f), c1 = make_float2(0.f, 0.f);
    const int rp_u = tid >> 6;          // stage1 unit: row-pair 0..7
    const int b_u  = tid & 63;          //              batch 0..63
    const int c4_a = tid >> 5;          // act unit (tid<128): h-col 0..3
    const int bp_a = tid & 31;          //                      batch-pair

    for (int k = 0; k <= T_; ++k) {
        ull acc[16];

        // ===== layer 0 at t = k =====
        if (k < T_) {
#pragma unroll
            for (int i = 0; i < 16; i++) acc[i] = 0ull;
            gemmY(acc, g_xT + k * I_ * B_, Wt0, I_ / 16, w, bo, rg);
            if (k > 0)
                gemmY(acc, g_h0buf + ((k - 1) & 1) * H_ * B_,
                      Wt0 + (I_ / 16) * 256, H_ / 16, w, bo, rg);
        }
        __syncthreads();                    // red free (prev iter readers done)
        if (k < T_) {
            ull* rw = red + w * 512 + (rg * 4) * 64 + bo * 4;
#pragma unroll
            for (int rpl = 0; rpl < 4; rpl++) {
                *(ulonglong2*)(rw + rpl * 64)     =
                    make_ulonglong2(acc[rpl * 4 + 0], acc[rpl * 4 + 1]);
                *(ulonglong2*)(rw + rpl * 64 + 2) =
                    make_ulonglong2(acc[rpl * 4 + 2], acc[rpl * 4 + 3]);
            }
        }
        __syncthreads();
        if (k < T_) {                       // stage1: 512 threads, 1 unit each
            const ull* rr = red + rp_u * 64 + b_u;
            ull v = rr[0];
#pragma unroll
            for (int ww = 1; ww < 16; ww++) v = addx2(v, rr[ww * 512]);
            float2 bb = *(const float2*)(bias0 + 2 * rp_u);
            v = addx2(v, pack_ab(bb.x, bb.y));
            gs[(2 * rp_u) * 64 + b_u]     = lo2(v);
            gs[(2 * rp_u + 1) * 64 + b_u] = hi2(v);
        }
        __syncthreads();
        if (k < T_ && tid < 128) {          // act0 — overlaps GEMM1 below
            float2 xi = *(const float2*)(gs + (0  + c4_a) * 64 + 2 * bp_a);
            float2 xf = *(const float2*)(gs + (4  + c4_a) * 64 + 2 * bp_a);
            float2 xg = *(const float2*)(gs + (8  + c4_a) * 64 + 2 * bp_a);
            float2 xo = *(const float2*)(gs + (12 + c4_a) * 64 + 2 * bp_a);
            float i0 = sigm(xi.x), i1 = sigm(xi.y);
            float f0 = sigm(xf.x), f1 = sigm(xf.y);
            float g0 = tanh_(xg.x), g1 = tanh_(xg.y);
            float o0 = sigm(xo.x), o1 = sigm(xo.y);
            c0.x = f0 * c0.x + i0 * g0;
            c0.y = f1 * c0.y + i1 * g1;
            *(float2*)(g_h0buf + (k & 1) * H_ * B_ + hj0 * B_
                       + c4_a * B_ + 2 * bp_a) =
                make_float2(o0 * tanh_(c0.x), o1 * tanh_(c0.y));
        }

        // ===== layer 1 at s = k-1 =====
        if (k >= 1) {
            int s = k - 1;
#pragma unroll
            for (int i = 0; i < 16; i++) acc[i] = 0ull;
            gemmY(acc, g_h0buf + (s & 1) * H_ * B_, Wt1, H_ / 16, w, bo, rg);
            if (s > 0)
                gemmY(acc, g_h1 + (s - 1) * H_ * B_,
                      Wt1 + (H_ / 16) * 256, H_ / 16, w, bo, rg);
        }
        __syncthreads();                    // stage1_0 done -> red reusable
        if (k >= 1) {
            ull* rw = red + w * 512 + (rg * 4) * 64 + bo * 4;
#pragma unroll
            for (int rpl = 0; rpl < 4; rpl++) {
                *(ulonglong2*)(rw + rpl * 64)     =
                    make_ulonglong2(acc[rpl * 4 + 0], acc[rpl * 4 + 1]);
                *(ulonglong2*)(rw + rpl * 64 + 2) =
                    make_ulonglong2(acc[rpl * 4 + 2], acc[rpl * 4 + 3]);
            }
        }
        __syncthreads();
        if (k >= 1) {
            const ull* rr = red + rp_u * 64 + b_u;
            ull v = rr[0];
#pragma unroll
            for (int ww = 1; ww < 16; ww++) v = addx2(v, rr[ww * 512]);
            float2 bb = *(const float2*)(bias1 + 2 * rp_u);
            v = addx2(v, pack_ab(bb.x, bb.y));
            gs[(2 * rp_u) * 64 + b_u]     = lo2(v);
            gs[(2 * rp_u + 1) * 64 + b_u] = hi2(v);
        }
        __syncthreads();
        if (k >= 1 && tid < 128) {          // act1 — flows into gridbar sync
            float2 xi = *(const float2*)(gs + (0  + c4_a) * 64 + 2 * bp_a);
            float2 xf = *(const float2*)(gs + (4  + c4_a) * 64 + 2 * bp_a);
            float2 xg = *(const float2*)(gs + (8  + c4_a) * 64 + 2 * bp_a);
            float2 xo = *(const float2*)(gs + (12 + c4_a) * 64 + 2 * bp_a);
            float i0 = sigm(xi.x), i1 = sigm(xi.y);
            float f0 = sigm(xf.x), f1 = sigm(xf.y);
            float g0 = tanh_(xg.x), g1 = tanh_(xg.y);
            float o0 = sigm(xo.x), o1 = sigm(xo.y);
            c1.x = f0 * c1.x + i0 * g0;
            c1.y = f1 * c1.y + i1 * g1;
            *(float2*)(g_h1 + (k - 1) * H_ * B_ + hj0 * B_
                       + c4_a * B_ + 2 * bp_a) =
                make_float2(o0 * tanh_(c1.x), o1 * tanh_(c1.y));
        }
        gridbar(sense);
    }

    // ---- FC phase: out[b][t][o] = sum_h h1[t][h][b] * Wfc[o][h] + bfc[o]
    {
        float* w_s = sm;                  // 128 x 65 = 8320
        float* h_s = sm + 8320;           // 64 x 64  = 4096
        float* o_s = sm + 12416;          // 64 x 128 = 8192
        const int ot = tid & 15;          // o = ot + j*16
        const int bt = (tid >> 4) & 15;   // batches bt*4 .. bt*4+3 (tid<256 only)

        for (int t = blockIdx.x; t < T_; t += GRID0) {
            ull acc[16];
#pragma unroll
            for (int i = 0; i < 16; i++) acc[i] = 0ull;

            for (int kb = 0; kb < H_; kb += 64) {
                __syncthreads();
                for (int idx = tid; idx < O_ * 64; idx += NT) {
                    int o = idx >> 6, kk = idx & 63;
                    w_s[o * 65 + kk] = Wfc[o * H_ + kb + kk];
                }
                for (int idx = tid; idx < 64 * B_; idx += NT) {
                    h_s[idx] = g_h1[(t * H_ + kb) * B_ + idx];
                }
                __syncthreads();
                if (tid < 256) {
#pragma unroll 4
                    for (int kk = 0; kk < 64; kk++) {
                        ulonglong2 A = *(const ulonglong2*)(h_s + kk * B_ + bt * 4);
#pragma unroll
                        for (int j = 0; j < 8; j++) {
                            ull ww = pack2(w_s[(ot + j * 16) * 65 + kk]);
                            ffma2(acc[j * 2 + 0], A.x, ww);
                            ffma2(acc[j * 2 + 1], A.y, ww);
                        }
                    }
                }
            }
            __syncthreads();
            if (tid < 256) {
#pragma unroll
                for (int j = 0; j < 8; j++) {
                    int o = ot + j * 16;
                    o_s[(bt * 4 + 0) * O_ + o] = lo2(acc[j * 2 + 0]);
                    o_s[(bt * 4 + 1) * O_ + o] = hi2(acc[j * 2 + 0]);
                    o_s[(bt * 4 + 2) * O_ + o] = lo2(acc[j * 2 + 1]);
                    o_s[(bt * 4 + 3) * O_ + o] = hi2(acc[j * 2 + 1]);
                }
            }
            __syncthreads();
            for (int idx = tid; idx < B_ * O_; idx += NT) {
                int b = idx >> 7, o = idx & 127;
                out[(b * T_ + t) * O_ + o] = o_s[idx] + __ldg(&bfc[o]);
            }
        }
    }
}

// ---------------------------------------------------------------------------
extern "C" void kernel_launch(void* const* d_in, const int* in_sizes, int n_in,
                              void* d_out, int out_size) {
    const float* x     = (const float*)d_in[0];
    const float* W_ih0 = (const float*)d_in[1];
    const float* W_hh0 = (const float*)d_in[2];
    const float* b_ih0 = (const float*)d_in[3];
    const float* b_hh0 = (const float*)d_in[4];
    const float* W_ih1 = (const float*)d_in[5];
    const float* W_hh1 = (const float*)d_in[6];
    const float* b_ih1 = (const float*)d_in[7];
    const float* b_hh1 = (const float*)d_in[8];
    const float* W_fc  = (const float*)d_in[9];
    const float* b_fc  = (const float*)d_in[10];
    float* out = (float*)d_out;

    size_t smem = (size_t)(27680 * 4 + 65536);   // 176256 B
    cudaFuncSetAttribute(mega_kernel, cudaFuncAttributeMaxDynamicSharedMemorySize, (int)smem);

    mega_kernel<<<GRID0, NT, smem>>>(x, W_ih0, W_hh0, b_ih0, b_hh0,
                                     W_ih1, W_hh1, b_ih1, b_hh1,
                                     W_fc, b_fc, out);
}